// round 2
// baseline (speedup 1.0000x reference)
#include <cuda_runtime.h>
#include <math.h>

// ---------------- static scratch (no allocation allowed) ----------------
#define NMAX 100000
#define EMAX 1600000
#define GMAX 512
#define CMAX 16
#define VMAX 128

__device__ float g_hlin[NMAX * 16];   // current layer's linear features (stride 16, zero-padded)
__device__ float g_hout[NMAX * 16];   // GAT layer output (post-activation)
__device__ float g_as[NMAX];          // alpha_src per node
__device__ float g_ad[NMAX];          // alpha_dst per node
__device__ int   g_cnt[NMAX];         // in-degree histogram
__device__ int   g_rowptr[NMAX + 1];  // CSR row pointers (by dst)
__device__ int   g_cursor[NMAX];      // scatter cursors
__device__ int   g_col[EMAX];         // CSR columns = src node per edge
__device__ int   g_bsum[1024];        // scan block partials
__device__ float g_embW[VMAX * 16];   // embedding @ W1 table
__device__ float g_tabs[VMAX];        // embW @ a_src1
__device__ float g_tabd[VMAX];        // embW @ a_dst1
__device__ float g_psum[GMAX * CMAX]; // pooled sums
__device__ float g_pcnt[GMAX];        // pooled counts

__device__ __forceinline__ float lrelu(float x) { return x > 0.f ? x : 0.2f * x; }

// ---------------- precompute layer-1 tables ----------------
__global__ void k_prep(const float* __restrict__ emb, const float* __restrict__ W1,
                       const float* __restrict__ a_s, const float* __restrict__ a_d,
                       int V, int D, int H)
{
    int tid = threadIdx.x;
    for (int t = tid; t < V * H; t += blockDim.x) {
        int v = t / H, k = t % H;
        float s = 0.f;
        for (int d = 0; d < D; d++) s += emb[v * D + d] * W1[d * H + k];
        g_embW[v * 16 + k] = s;
    }
    // zero-pad unused columns (H == 16 in practice; defensive)
    for (int t = tid; t < V * 16; t += blockDim.x) {
        if ((t % 16) >= H) g_embW[t] = 0.f;
    }
    __syncthreads();
    for (int v = tid; v < V; v += blockDim.x) {
        float ss = 0.f, sd = 0.f;
        for (int k = 0; k < H; k++) {
            float e = g_embW[v * 16 + k];
            ss += e * a_s[k];
            sd += e * a_d[k];
        }
        g_tabs[v] = ss;
        g_tabd[v] = sd;
    }
}

// ---------------- argmax(x) per node + table lookup (warp per node) ----------------
__global__ void k_node_init(const float* __restrict__ x, int N, int V)
{
    int wid = (blockIdx.x * blockDim.x + threadIdx.x) >> 5;
    int lid = threadIdx.x & 31;
    if (wid >= N) return;
    const float* row = x + (long long)wid * V;
    float best = -INFINITY;
    int bidx = 0;
    for (int c = lid; c < V; c += 32) {
        float v = row[c];
        if (v > best) { best = v; bidx = c; }   // in-lane: strictly greater keeps first index
    }
#pragma unroll
    for (int o = 16; o; o >>= 1) {
        float ov = __shfl_xor_sync(0xffffffffu, best, o);
        int   oi = __shfl_xor_sync(0xffffffffu, bidx, o);
        if (ov > best || (ov == best && oi < bidx)) { best = ov; bidx = oi; }
    }
    if (lid < 16) g_hlin[wid * 16 + lid] = g_embW[bidx * 16 + lid];
    if (lid == 0) { g_as[wid] = g_tabs[bidx]; g_ad[wid] = g_tabd[bidx]; }
}

// ---------------- CSR build ----------------
__global__ void k_zero_cnt(int N)
{
    int i = blockIdx.x * blockDim.x + threadIdx.x;
    if (i < N) g_cnt[i] = 0;
}

__global__ void k_hist(const int* __restrict__ ei, int E)
{
    int e = blockIdx.x * blockDim.x + threadIdx.x;
    if (e < E) atomicAdd(&g_cnt[ei[E + e]], 1);
}

__device__ int block_exscan(int v, int* p_total)
{
    int lane = threadIdx.x & 31, w = threadIdx.x >> 5;
    int x = v;
#pragma unroll
    for (int o = 1; o < 32; o <<= 1) {
        int y = __shfl_up_sync(0xffffffffu, x, o);
        if (lane >= o) x += y;
    }
    __shared__ int ws[32];
    if (lane == 31) ws[w] = x;
    __syncthreads();
    int nw = (blockDim.x + 31) >> 5;
    if (w == 0) {
        int z = (lane < nw) ? ws[lane] : 0;
#pragma unroll
        for (int o = 1; o < 32; o <<= 1) {
            int y = __shfl_up_sync(0xffffffffu, z, o);
            if (lane >= o) z += y;
        }
        ws[lane] = z;
    }
    __syncthreads();
    int off = (w > 0) ? ws[w - 1] : 0;
    int total = ws[nw - 1];
    if (p_total) *p_total = total;
    return off + x - v;
}

__global__ void k_scan1(int N)
{
    int idx = blockIdx.x * 1024 + threadIdx.x;
    int v = (idx < N) ? g_cnt[idx] : 0;
    int tot;
    block_exscan(v, &tot);
    if (threadIdx.x == 0) g_bsum[blockIdx.x] = tot;
}

__global__ void k_scan2(int B, int N)
{
    int v = ((int)threadIdx.x < B) ? g_bsum[threadIdx.x] : 0;
    int tot;
    int ex = block_exscan(v, &tot);
    if ((int)threadIdx.x < B) g_bsum[threadIdx.x] = ex;
    if (threadIdx.x == 0) g_rowptr[N] = tot;
}

__global__ void k_scan3(int N)
{
    int idx = blockIdx.x * 1024 + threadIdx.x;
    int v = (idx < N) ? g_cnt[idx] : 0;
    int ex = block_exscan(v, nullptr) + g_bsum[blockIdx.x];
    if (idx < N) { g_rowptr[idx] = ex; g_cursor[idx] = ex; }
}

__global__ void k_scatter(const int* __restrict__ ei, int E)
{
    int e = blockIdx.x * blockDim.x + threadIdx.x;
    if (e < E) {
        int d = ei[E + e];
        int pos = atomicAdd(&g_cursor[d], 1);
        g_col[pos] = ei[e];
    }
}

// ---------------- GAT layer: warp per destination node, no atomics ----------------
// self-loop handled analytically; softmax denom applied after aggregation
template <int F, bool RELU>
__global__ void k_gat(const float* __restrict__ bias, int N)
{
    int wid = (blockIdx.x * blockDim.x + threadIdx.x) >> 5;
    int lid = threadIdx.x & 31;
    if (wid >= N) return;
    int n = wid;
    int beg = g_rowptr[n], end = g_rowptr[n + 1];
    float adn = g_ad[n];
    float e_self = lrelu(g_as[n] + adn);

    // pass 1: segment max (self-loop included via init)
    float m = e_self;
    for (int j = beg + lid; j < end; j += 32)
        m = fmaxf(m, lrelu(g_as[g_col[j]] + adn));
#pragma unroll
    for (int o = 16; o; o >>= 1) m = fmaxf(m, __shfl_xor_sync(0xffffffffu, m, o));

    // pass 2: denom + weighted feature aggregation (half-warp: (pair, feature))
    int k = lid & 15, pe = lid >> 4;
    float p_self = __expf(e_self - m);
    float den = (lid == 0) ? p_self : 0.f;
    float acc = (pe == 0) ? p_self * g_hlin[n * 16 + k] : 0.f;

    for (int c = beg; c < end; c += 32) {
        int j = c + lid;
        int s = 0;
        float p = 0.f;
        if (j < end) {
            s = g_col[j];
            p = __expf(lrelu(g_as[s] + adn) - m);
        }
        den += p;
        int cnt = min(32, end - c);
        for (int jj = 0; jj < cnt; jj += 2) {
            int lane = jj + pe;                          // lane==cnt has p=0, harmless
            int   ss = __shfl_sync(0xffffffffu, s, lane);
            float pp = __shfl_sync(0xffffffffu, p, lane);
            acc += pp * g_hlin[ss * 16 + k];             // 64B coalesced per half-warp
        }
    }
#pragma unroll
    for (int o = 16; o; o >>= 1) den += __shfl_xor_sync(0xffffffffu, den, o);
    acc += __shfl_xor_sync(0xffffffffu, acc, 16);        // merge even/odd edge halves

    if (pe == 0 && k < F) {
        float v = acc / den + bias[k];
        if (RELU) v = fmaxf(v, 0.f);
        g_hout[n * 16 + k] = v;
    }
}

// ---------------- inter-layer linear: h@W, alpha_src, alpha_dst ----------------
template <int FOUT>
__global__ void k_lin(const float* __restrict__ W, const float* __restrict__ av,
                      const float* __restrict__ dv, int N)
{
    __shared__ float sW[16 * FOUT];
    __shared__ float sa[FOUT], sd[FOUT];
    for (int i = threadIdx.x; i < 16 * FOUT; i += blockDim.x) sW[i] = W[i];
    if (threadIdx.x < FOUT) { sa[threadIdx.x] = av[threadIdx.x]; sd[threadIdx.x] = dv[threadIdx.x]; }
    __syncthreads();
    int n = blockIdx.x * blockDim.x + threadIdx.x;
    if (n >= N) return;
    float h[16];
    const float4* hp = (const float4*)(g_hout + n * 16);
#pragma unroll
    for (int q = 0; q < 4; q++) {
        float4 f = hp[q];
        h[q * 4] = f.x; h[q * 4 + 1] = f.y; h[q * 4 + 2] = f.z; h[q * 4 + 3] = f.w;
    }
    float out[16];
    float as_ = 0.f, ad_ = 0.f;
#pragma unroll
    for (int kk = 0; kk < FOUT; kk++) {
        float s = 0.f;
#pragma unroll
        for (int j = 0; j < 16; j++) s += h[j] * sW[j * FOUT + kk];
        out[kk] = s;
        as_ += s * sa[kk];
        ad_ += s * sd[kk];
    }
#pragma unroll
    for (int kk = FOUT; kk < 16; kk++) out[kk] = 0.f;
    float4* op = (float4*)(g_hlin + n * 16);
#pragma unroll
    for (int q = 0; q < 4; q++)
        op[q] = make_float4(out[q * 4], out[q * 4 + 1], out[q * 4 + 2], out[q * 4 + 3]);
    g_as[n] = as_;
    g_ad[n] = ad_;
}

// ---------------- global mean pool + softmax ----------------
__global__ void k_zero_pool(int G, int C)
{
    int i = blockIdx.x * blockDim.x + threadIdx.x;
    if (i < G * C) g_psum[i] = 0.f;
    if (i < G) g_pcnt[i] = 0.f;
}

template <int C>
__global__ void k_pool(const int* __restrict__ batch, int N)
{
    int n = blockIdx.x * blockDim.x + threadIdx.x;
    bool valid = n < N;
    int g = valid ? batch[n] : -1;
    float v[C];
#pragma unroll
    for (int k = 0; k < C; k++) v[k] = valid ? g_hout[n * 16 + k] : 0.f;
    int g0 = __shfl_sync(0xffffffffu, g, 0);
    bool uni = __all_sync(0xffffffffu, g == g0);
    if (uni) {   // batch sorted -> common case: whole warp same graph
#pragma unroll
        for (int k = 0; k < C; k++)
#pragma unroll
            for (int o = 16; o; o >>= 1) v[k] += __shfl_xor_sync(0xffffffffu, v[k], o);
        if ((threadIdx.x & 31) == 0 && g0 >= 0) {
#pragma unroll
            for (int k = 0; k < C; k++) atomicAdd(&g_psum[g0 * C + k], v[k]);
            atomicAdd(&g_pcnt[g0], 32.f);
        }
    } else if (valid) {
#pragma unroll
        for (int k = 0; k < C; k++) atomicAdd(&g_psum[g * C + k], v[k]);
        atomicAdd(&g_pcnt[g], 1.f);
    }
}

__global__ void k_softmax(float* __restrict__ out, int G, int C)
{
    int wid = (blockIdx.x * blockDim.x + threadIdx.x) >> 5;
    int lid = threadIdx.x & 31;
    if (wid >= G) return;
    float val = (lid < C) ? g_psum[wid * C + lid] / fmaxf(g_pcnt[wid], 1.f) : -INFINITY;
    float mm = val;
#pragma unroll
    for (int o = 16; o; o >>= 1) mm = fmaxf(mm, __shfl_xor_sync(0xffffffffu, mm, o));
    float p = (lid < C) ? __expf(val - mm) : 0.f;
    float s = p;
#pragma unroll
    for (int o = 16; o; o >>= 1) s += __shfl_xor_sync(0xffffffffu, s, o);
    if (lid < C) out[wid * C + lid] = p / s;
}

// ---------------- launch ----------------
extern "C" void kernel_launch(void* const* d_in, const int* in_sizes, int n_in,
                              void* d_out, int out_size)
{
    const float* x    = (const float*)d_in[0];
    const int*   ei   = (const int*)d_in[1];
    const int*   batch= (const int*)d_in[2];
    const float* emb  = (const float*)d_in[3];
    const float* W1   = (const float*)d_in[4];
    const float* as1  = (const float*)d_in[5];
    const float* ad1  = (const float*)d_in[6];
    const float* b1   = (const float*)d_in[7];
    const float* W2   = (const float*)d_in[8];
    const float* as2  = (const float*)d_in[9];
    const float* ad2  = (const float*)d_in[10];
    const float* b2   = (const float*)d_in[11];
    const float* W3   = (const float*)d_in[12];
    const float* as3  = (const float*)d_in[13];
    const float* ad3  = (const float*)d_in[14];
    const float* b3   = (const float*)d_in[15];
    float* out = (float*)d_out;

    int H = in_sizes[5];                 // 16
    int C = in_sizes[13];                // 10
    int D = in_sizes[4] / H;             // 50
    int V = in_sizes[3] / D;             // 128
    int N = in_sizes[0] / V;             // 100000
    int E = in_sizes[1] / 2;             // 1600000
    int G = out_size / C;                // 512

    // layer-1 tables
    k_prep<<<1, 256>>>(emb, W1, as1, ad1, V, D, H);

    // argmax + embedding/linear lookup
    int niBlocks = (N * 32 + 255) / 256;
    k_node_init<<<niBlocks, 256>>>(x, N, V);

    // CSR build (by dst), reused by all 3 layers
    k_zero_cnt<<<(N + 255) / 256, 256>>>(N);
    k_hist<<<(E + 255) / 256, 256>>>(ei, E);
    int B = (N + 1023) / 1024;
    k_scan1<<<B, 1024>>>(N);
    k_scan2<<<1, 1024>>>(B, N);
    k_scan3<<<B, 1024>>>(N);
    k_scatter<<<(E + 255) / 256, 256>>>(ei, E);

    // 3 GAT layers
    int gatBlocks = (N * 32 + 255) / 256;
    k_gat<16, true><<<gatBlocks, 256>>>(b1, N);
    k_lin<16><<<(N + 255) / 256, 256>>>(W2, as2, ad2, N);
    k_gat<16, true><<<gatBlocks, 256>>>(b2, N);
    k_lin<10><<<(N + 255) / 256, 256>>>(W3, as3, ad3, N);
    k_gat<10, false><<<gatBlocks, 256>>>(b3, N);

    // pool + softmax
    k_zero_pool<<<(G * C + 255) / 256, 256>>>(G, C);
    k_pool<10><<<(N + 255) / 256, 256>>>(batch, N);
    k_softmax<<<(G * 32 + 255) / 256, 256>>>(out, G, C);
}

// round 3
// speedup vs baseline: 1.2418x; 1.2418x over previous
#include <cuda_runtime.h>
#include <math.h>

// ---------------- static scratch (no allocation allowed) ----------------
#define NMAX 100000
#define EMAX 1600000
#define GMAX 512
#define CMAX 16
#define VMAX 128

__device__ float g_hlin[NMAX * 16];   // current layer's linear features (stride 16, zero-padded)
__device__ float g_hout[NMAX * 16];   // GAT layer output (post-activation)
__device__ float g_as[NMAX];          // alpha_src per node
__device__ float g_ad[NMAX];          // alpha_dst per node
__device__ int   g_cnt[NMAX];         // in-degree histogram
__device__ int   g_rowptr[NMAX + 1];  // CSR row pointers (by dst)
__device__ int   g_cursor[NMAX];      // scatter cursors
__device__ int   g_col[EMAX];         // CSR columns = src node per edge
__device__ int   g_bsum[1024];        // scan block partials
__device__ float g_embW[VMAX * 16];   // embedding @ W1 table
__device__ float g_tabs[VMAX];        // embW @ a_src1
__device__ float g_tabd[VMAX];        // embW @ a_dst1
__device__ float g_psum[GMAX * CMAX]; // pooled sums
__device__ float g_pcnt[GMAX];        // pooled counts

__device__ __forceinline__ float lrelu(float x) { return x > 0.f ? x : 0.2f * x; }

// ---------------- precompute layer-1 tables + zero scratch (fused) ----------------
__global__ void k_prep(const float* __restrict__ emb, const float* __restrict__ W1,
                       const float* __restrict__ a_s, const float* __restrict__ a_d,
                       int V, int D, int H, int N, int G, int C)
{
    int gtid = blockIdx.x * blockDim.x + threadIdx.x;
    int gstr = gridDim.x * blockDim.x;
    // zero degree histogram + pool accumulators (all blocks)
    for (int i = gtid; i < N; i += gstr) g_cnt[i] = 0;
    if (gtid < G * C) g_psum[gtid] = 0.f;
    if (gtid < G) g_pcnt[gtid] = 0.f;

    // block 0 computes the embedding@W1 tables
    if (blockIdx.x != 0) return;
    int tid = threadIdx.x;
    for (int t = tid; t < V * 16; t += blockDim.x) {
        int v = t >> 4, k = t & 15;
        float s = 0.f;
        if (k < H)
            for (int d = 0; d < D; d++) s += emb[v * D + d] * W1[d * H + k];
        g_embW[v * 16 + k] = s;
    }
    __syncthreads();
    for (int v = tid; v < V; v += blockDim.x) {
        float ss = 0.f, sd = 0.f;
        for (int k = 0; k < H; k++) {
            float e = g_embW[v * 16 + k];
            ss += e * a_s[k];
            sd += e * a_d[k];
        }
        g_tabs[v] = ss;
        g_tabd[v] = sd;
    }
}

// ---------------- argmax(x) per node + table lookup (warp per node, float4) ----------------
__global__ void k_node_init(const float* __restrict__ x, int N, int V)
{
    int wid = (blockIdx.x * blockDim.x + threadIdx.x) >> 5;
    int lid = threadIdx.x & 31;
    if (wid >= N) return;
    const float4* row = (const float4*)(x + (long long)wid * V);
    int V4 = V >> 2;
    float best = -INFINITY;
    int bidx = 0;
    for (int c = lid; c < V4; c += 32) {
        float4 f = row[c];
        int base = c * 4;
        if (f.x > best) { best = f.x; bidx = base; }
        if (f.y > best) { best = f.y; bidx = base + 1; }
        if (f.z > best) { best = f.z; bidx = base + 2; }
        if (f.w > best) { best = f.w; bidx = base + 3; }
    }
#pragma unroll
    for (int o = 16; o; o >>= 1) {
        float ov = __shfl_xor_sync(0xffffffffu, best, o);
        int   oi = __shfl_xor_sync(0xffffffffu, bidx, o);
        if (ov > best || (ov == best && oi < bidx)) { best = ov; bidx = oi; }
    }
    if (lid < 4)
        ((float4*)g_hlin)[wid * 4 + lid] = ((const float4*)g_embW)[bidx * 4 + lid];
    if (lid == 0) { g_as[wid] = g_tabs[bidx]; g_ad[wid] = g_tabd[bidx]; }
}

// ---------------- CSR build ----------------
__global__ void k_hist(const int* __restrict__ ei, int E)
{
    int t = blockIdx.x * blockDim.x + threadIdx.x;
    int i0 = t * 2;
    if (i0 < E)     atomicAdd(&g_cnt[ei[E + i0]], 1);
    if (i0 + 1 < E) atomicAdd(&g_cnt[ei[E + i0 + 1]], 1);
}

__device__ int block_exscan(int v, int* p_total)
{
    int lane = threadIdx.x & 31, w = threadIdx.x >> 5;
    int x = v;
#pragma unroll
    for (int o = 1; o < 32; o <<= 1) {
        int y = __shfl_up_sync(0xffffffffu, x, o);
        if (lane >= o) x += y;
    }
    __shared__ int ws[32];
    if (lane == 31) ws[w] = x;
    __syncthreads();
    int nw = (blockDim.x + 31) >> 5;
    if (w == 0) {
        int z = (lane < nw) ? ws[lane] : 0;
#pragma unroll
        for (int o = 1; o < 32; o <<= 1) {
            int y = __shfl_up_sync(0xffffffffu, z, o);
            if (lane >= o) z += y;
        }
        ws[lane] = z;
    }
    __syncthreads();
    int off = (w > 0) ? ws[w - 1] : 0;
    int total = ws[nw - 1];
    if (p_total) *p_total = total;
    return off + x - v;
}

__global__ void k_scan1(int N)
{
    int idx = blockIdx.x * 1024 + threadIdx.x;
    int v = (idx < N) ? g_cnt[idx] : 0;
    int tot;
    block_exscan(v, &tot);
    if (threadIdx.x == 0) g_bsum[blockIdx.x] = tot;
}

__global__ void k_scan2(int B, int N)
{
    int v = ((int)threadIdx.x < B) ? g_bsum[threadIdx.x] : 0;
    int tot;
    int ex = block_exscan(v, &tot);
    if ((int)threadIdx.x < B) g_bsum[threadIdx.x] = ex;
    if (threadIdx.x == 0) g_rowptr[N] = tot;
}

__global__ void k_scan3(int N)
{
    int idx = blockIdx.x * 1024 + threadIdx.x;
    int v = (idx < N) ? g_cnt[idx] : 0;
    int ex = block_exscan(v, nullptr) + g_bsum[blockIdx.x];
    if (idx < N) { g_rowptr[idx] = ex; g_cursor[idx] = ex; }
}

__global__ void k_scatter(const int* __restrict__ ei, int E)
{
    int e = blockIdx.x * blockDim.x + threadIdx.x;
    if (e < E) {
        int d = ei[E + e];
        int pos = atomicAdd(&g_cursor[d], 1);
        g_col[pos] = ei[e];
    }
}

// ---------------- GAT layer: warp per destination node, single pass ----------------
// Softmax is shift-invariant and |e| is small (O(10) << 88), so we use the
// unshifted exp: p = exp(e), alpha = p / sum(p). No segment-max pass needed.
// Lane layout for aggregation: (edge-slot e8 = lid>>2, feature-quad q = lid&3),
// each lane accumulates a float4 of features -> 4 inner iterations per 32 edges.
template <int F, bool RELU>
__global__ void k_gat(const float* __restrict__ bias, int N)
{
    int wid = (blockIdx.x * blockDim.x + threadIdx.x) >> 5;
    int lid = threadIdx.x & 31;
    if (wid >= N) return;
    int n = wid;
    int beg = g_rowptr[n], end = g_rowptr[n + 1];
    float adn = g_ad[n];
    float p_self = __expf(lrelu(g_as[n] + adn));

    int q = lid & 3, e8 = lid >> 2;
    const float4* h4 = (const float4*)g_hlin;

    float den = (lid == 0) ? p_self : 0.f;
    float4 acc = make_float4(0.f, 0.f, 0.f, 0.f);
    if (e8 == 0) {   // self-loop contribution
        float4 hv = h4[n * 4 + q];
        acc.x = p_self * hv.x; acc.y = p_self * hv.y;
        acc.z = p_self * hv.z; acc.w = p_self * hv.w;
    }

    for (int c = beg; c < end; c += 32) {
        int j = c + lid;
        int s = 0;
        float p = 0.f;
        if (j < end) {
            s = g_col[j];
            p = __expf(lrelu(g_as[s] + adn));
        }
        den += p;
        int cnt = min(32, end - c);
        for (int jj = 0; jj < cnt; jj += 8) {
            int lane = jj + e8;                 // lane >= cnt has p=0 -> harmless
            int   ss = __shfl_sync(0xffffffffu, s, lane);
            float pp = __shfl_sync(0xffffffffu, p, lane);
            float4 hv = h4[ss * 4 + q];         // 64B coalesced per 4-lane group
            acc.x += pp * hv.x; acc.y += pp * hv.y;
            acc.z += pp * hv.z; acc.w += pp * hv.w;
        }
    }
#pragma unroll
    for (int o = 16; o; o >>= 1) den += __shfl_xor_sync(0xffffffffu, den, o);
#pragma unroll
    for (int o = 4; o <= 16; o <<= 1) {
        acc.x += __shfl_xor_sync(0xffffffffu, acc.x, o);
        acc.y += __shfl_xor_sync(0xffffffffu, acc.y, o);
        acc.z += __shfl_xor_sync(0xffffffffu, acc.z, o);
        acc.w += __shfl_xor_sync(0xffffffffu, acc.w, o);
    }

    if (lid < 4) {
        float inv = 1.f / den;
        int k0 = q * 4;
        float o0 = (k0 + 0 < F) ? acc.x * inv + bias[k0 + 0] : 0.f;
        float o1 = (k0 + 1 < F) ? acc.y * inv + bias[k0 + 1] : 0.f;
        float o2 = (k0 + 2 < F) ? acc.z * inv + bias[k0 + 2] : 0.f;
        float o3 = (k0 + 3 < F) ? acc.w * inv + bias[k0 + 3] : 0.f;
        if (RELU) {
            o0 = fmaxf(o0, 0.f); o1 = fmaxf(o1, 0.f);
            o2 = fmaxf(o2, 0.f); o3 = fmaxf(o3, 0.f);
        }
        ((float4*)g_hout)[n * 4 + q] = make_float4(o0, o1, o2, o3);
    }
}

// ---------------- inter-layer linear: h@W, alpha_src, alpha_dst ----------------
template <int FOUT>
__global__ void k_lin(const float* __restrict__ W, const float* __restrict__ av,
                      const float* __restrict__ dv, int N)
{
    __shared__ float sW[16 * FOUT];
    __shared__ float sa[FOUT], sd[FOUT];
    for (int i = threadIdx.x; i < 16 * FOUT; i += blockDim.x) sW[i] = W[i];
    if (threadIdx.x < FOUT) { sa[threadIdx.x] = av[threadIdx.x]; sd[threadIdx.x] = dv[threadIdx.x]; }
    __syncthreads();
    int n = blockIdx.x * blockDim.x + threadIdx.x;
    if (n >= N) return;
    float h[16];
    const float4* hp = (const float4*)(g_hout + n * 16);
#pragma unroll
    for (int qq = 0; qq < 4; qq++) {
        float4 f = hp[qq];
        h[qq * 4] = f.x; h[qq * 4 + 1] = f.y; h[qq * 4 + 2] = f.z; h[qq * 4 + 3] = f.w;
    }
    float out[16];
    float as_ = 0.f, ad_ = 0.f;
#pragma unroll
    for (int kk = 0; kk < FOUT; kk++) {
        float s = 0.f;
#pragma unroll
        for (int j = 0; j < 16; j++) s += h[j] * sW[j * FOUT + kk];
        out[kk] = s;
        as_ += s * sa[kk];
        ad_ += s * sd[kk];
    }
#pragma unroll
    for (int kk = FOUT; kk < 16; kk++) out[kk] = 0.f;
    float4* op = (float4*)(g_hlin + n * 16);
#pragma unroll
    for (int qq = 0; qq < 4; qq++)
        op[qq] = make_float4(out[qq * 4], out[qq * 4 + 1], out[qq * 4 + 2], out[qq * 4 + 3]);
    g_as[n] = as_;
    g_ad[n] = ad_;
}

// ---------------- global mean pool + softmax ----------------
template <int C>
__global__ void k_pool(const int* __restrict__ batch, int N)
{
    int n = blockIdx.x * blockDim.x + threadIdx.x;
    bool valid = n < N;
    int g = valid ? batch[n] : -1;
    float v[C];
#pragma unroll
    for (int k = 0; k < C; k++) v[k] = valid ? g_hout[n * 16 + k] : 0.f;
    int g0 = __shfl_sync(0xffffffffu, g, 0);
    bool uni = __all_sync(0xffffffffu, g == g0);
    if (uni) {   // batch sorted -> common case: whole warp same graph
#pragma unroll
        for (int k = 0; k < C; k++)
#pragma unroll
            for (int o = 16; o; o >>= 1) v[k] += __shfl_xor_sync(0xffffffffu, v[k], o);
        if ((threadIdx.x & 31) == 0 && g0 >= 0) {
#pragma unroll
            for (int k = 0; k < C; k++) atomicAdd(&g_psum[g0 * C + k], v[k]);
            atomicAdd(&g_pcnt[g0], 32.f);
        }
    } else if (valid) {
#pragma unroll
        for (int k = 0; k < C; k++) atomicAdd(&g_psum[g * C + k], v[k]);
        atomicAdd(&g_pcnt[g], 1.f);
    }
}

__global__ void k_softmax(float* __restrict__ out, int G, int C)
{
    int wid = (blockIdx.x * blockDim.x + threadIdx.x) >> 5;
    int lid = threadIdx.x & 31;
    if (wid >= G) return;
    float val = (lid < C) ? g_psum[wid * C + lid] / fmaxf(g_pcnt[wid], 1.f) : -INFINITY;
    float mm = val;
#pragma unroll
    for (int o = 16; o; o >>= 1) mm = fmaxf(mm, __shfl_xor_sync(0xffffffffu, mm, o));
    float p = (lid < C) ? __expf(val - mm) : 0.f;
    float s = p;
#pragma unroll
    for (int o = 16; o; o >>= 1) s += __shfl_xor_sync(0xffffffffu, s, o);
    if (lid < C) out[wid * C + lid] = p / s;
}

// ---------------- launch ----------------
extern "C" void kernel_launch(void* const* d_in, const int* in_sizes, int n_in,
                              void* d_out, int out_size)
{
    const float* x    = (const float*)d_in[0];
    const int*   ei   = (const int*)d_in[1];
    const int*   batch= (const int*)d_in[2];
    const float* emb  = (const float*)d_in[3];
    const float* W1   = (const float*)d_in[4];
    const float* as1  = (const float*)d_in[5];
    const float* ad1  = (const float*)d_in[6];
    const float* b1   = (const float*)d_in[7];
    const float* W2   = (const float*)d_in[8];
    const float* as2  = (const float*)d_in[9];
    const float* ad2  = (const float*)d_in[10];
    const float* b2   = (const float*)d_in[11];
    const float* W3   = (const float*)d_in[12];
    const float* as3  = (const float*)d_in[13];
    const float* ad3  = (const float*)d_in[14];
    const float* b3   = (const float*)d_in[15];
    float* out = (float*)d_out;

    int H = in_sizes[5];                 // 16
    int C = in_sizes[13];                // 10
    int D = in_sizes[4] / H;             // 50
    int V = in_sizes[3] / D;             // 128
    int N = in_sizes[0] / V;             // 100000
    int E = in_sizes[1] / 2;             // 1600000
    int G = out_size / C;                // 512

    // tables + zero scratch (fused)
    k_prep<<<200, 256>>>(emb, W1, as1, ad1, V, D, H, N, G, C);

    // argmax + embedding/linear lookup
    int niBlocks = (N * 32 + 255) / 256;
    k_node_init<<<niBlocks, 256>>>(x, N, V);

    // CSR build (by dst), reused by all 3 layers
    k_hist<<<(E / 2 + 255) / 256, 256>>>(ei, E);
    int B = (N + 1023) / 1024;
    k_scan1<<<B, 1024>>>(N);
    k_scan2<<<1, 1024>>>(B, N);
    k_scan3<<<B, 1024>>>(N);
    k_scatter<<<(E + 255) / 256, 256>>>(ei, E);

    // 3 GAT layers (single-pass softmax)
    int gatBlocks = (N * 32 + 255) / 256;
    k_gat<16, true><<<gatBlocks, 256>>>(b1, N);
    k_lin<16><<<(N + 255) / 256, 256>>>(W2, as2, ad2, N);
    k_gat<16, true><<<gatBlocks, 256>>>(b2, N);
    k_lin<10><<<(N + 255) / 256, 256>>>(W3, as3, ad3, N);
    k_gat<10, false><<<gatBlocks, 256>>>(b3, N);

    // pool + softmax
    k_pool<10><<<(N + 255) / 256, 256>>>(batch, N);
    k_softmax<<<(G * 32 + 255) / 256, 256>>>(out, G, C);
}